// round 16
// baseline (speedup 1.0000x reference)
#include <cuda_runtime.h>
#include <math_constants.h>
#include <cstdint>

#define NPTS 16384
#define KK 10
#define CB 64
#define NBIN 4096

// knn64 tiling: 64-row chunks, 128-col tiles, 128 threads (8x8 micro-tile)
#define KNT 128                 /* col tiles */
#define KNCH 256                /* row chunks = grid */

// dynamic smem layout for knn64 (bytes) — 100128 total => 2 blocks/SM
#define SM_SCOL   0             /* 2 x 32768 swizzled col tiles */
#define SM_SROW   65536         /* 16384 swizzled row tile (64 rows) */
#define SM_SDIST  81920         /* 64 rows x 64 cols floats = 16384 (half-col passes) */
#define SM_SSQ    98304         /* 2 x 128 col norms */
#define SM_SIDX   99328         /* 2 x 128 uint16 col orig idx = 512 */
#define SM_RN     99840         /* 64 row norms */
#define SM_CTL    100096        /* control: 3 ints + 4 floats = 32 */
#define SMEM_K    100128

// ---------------- scratch (device globals; no allocation) ----------------
__device__ __align__(16) float d_sq[NPTS];
__device__ int   d_idx[NPTS*KK];
__device__ __align__(16) float d_f1[NPTS*CB];
__device__ __align__(16) float d_f2[NPTS*CB];
__device__ __align__(16) float d_f3[NPTS*CB];
__device__ __align__(16) float d_f4[NPTS*CB];
__device__ __align__(16) float d_fperm[NPTS*CB];
__device__ __align__(16) float d_skey[NPTS];
__device__ __align__(16) unsigned short d_sidx16[NPTS];
__device__ __align__(16) float d_pmax[KNT];
__device__ __align__(16) float d_pmin[KNT];
__device__ __align__(16) float d_Abuf[NPTS*CB];
__device__ __align__(16) float d_Cbuf[NPTS*CB];
__device__ __align__(16) float d_maxh[NPTS*CB];
__device__ __align__(16) float d_minh[NPTS*CB];
__device__ float d_sum[CB];
__device__ float d_ss[CB];
__device__ int   d_starts[65];
__device__ float d_P[64*256];

// Resolve feature-buffer id -> device pointer IN DEVICE CODE (host-side
// __device__ symbol decay passes the host shadow address under ATS).
__device__ __forceinline__ float* fbuf(int id){
    switch(id){
        case 1: return d_f1;
        case 2: return d_f2;
        case 3: return d_f3;
        default: return d_f4;
    }
}

// ---------------- packed f32x2 helpers ----------------
__device__ __forceinline__ unsigned long long ffma2(unsigned long long a, unsigned long long b, unsigned long long c){
    unsigned long long r;
    asm("fma.rn.f32x2 %0, %1, %2, %3;" : "=l"(r) : "l"(a), "l"(b), "l"(c));
    return r;
}
__device__ __forceinline__ float hsum2(unsigned long long v){
    float lo, hi;
    asm("mov.b64 {%0,%1}, %2;" : "=f"(lo), "=f"(hi) : "l"(v));
    return lo + hi;
}

// ---------------- cp.async helpers ----------------
__device__ __forceinline__ unsigned smaddr(const void* p){
    return (unsigned)__cvta_generic_to_shared(p);
}
__device__ __forceinline__ void cp16(unsigned s, const void* g){
    asm volatile("cp.async.cg.shared.global [%0], [%1], 16;" :: "r"(s), "l"(g));
}
__device__ __forceinline__ void cp_commit(){ asm volatile("cp.async.commit_group;"); }
__device__ __forceinline__ void cp_wait0(){ asm volatile("cp.async.wait_group 0;"); }

// ---------------- launch 1: fused kNN(3D) + projection(C=3) + stat reset ----
__global__ __launch_bounds__(128) void knn3proj3_kernel(const float* __restrict__ x,
                                                        const float* __restrict__ W){
    __shared__ float sWa[192], sWb[192];
    __shared__ float4 sc[256];
    const int t = threadIdx.x;
    const int i = blockIdx.x*128 + t;
    for (int v = t; v < 192; v += 128){
        float wb = W[192 + v];
        sWa[v] = W[v] - wb;
        sWb[v] = wb;
    }
    if (blockIdx.x == 0 && t < 64){ d_sum[t] = 0.f; d_ss[t] = 0.f; }
    float xi = x[i*3], yi = x[i*3+1], zi = x[i*3+2];
    float sqi = xi*xi + yi*yi + zi*zi;
    __syncthreads();

    #pragma unroll 8
    for (int o = 0; o < 64; o++){
        float av = xi*sWa[o] + yi*sWa[64+o] + zi*sWa[128+o];
        float cv = xi*sWb[o] + yi*sWb[64+o] + zi*sWb[128+o];
        d_Abuf[i*64+o] = av; d_Cbuf[i*64+o] = cv;
    }

    float bd[KK]; int bi[KK];
    #pragma unroll
    for (int q = 0; q < KK; q++){ bd[q] = CUDART_INF_F; bi[q] = 0x7fffffff; }
    for (int base = 0; base < NPTS; base += 256){
        __syncthreads();
        for (int v = t; v < 256; v += 128){
            int c = base + v;
            float xc = x[c*3], yc = x[c*3+1], zc = x[c*3+2];
            sc[v] = make_float4(xc, yc, zc, xc*xc + yc*yc + zc*zc);
        }
        __syncthreads();
        #pragma unroll 4
        for (int j = 0; j < 256; j++){
            float4 cv = sc[j];
            float dist = sqi + cv.w - 2.f*(xi*cv.x + yi*cv.y + zi*cv.z);
            if (dist < bd[KK-1]){
                float cd = dist; int ci = base + j;
                #pragma unroll
                for (int q = 0; q < KK; q++){
                    if (cd < bd[q]){ float td = bd[q]; int ti = bi[q]; bd[q] = cd; bi[q] = ci; cd = td; ci = ti; }
                }
            }
        }
    }
    #pragma unroll
    for (int q = 0; q < KK; q++) d_idx[i*KK+q] = bi[q];
}

// ---------------- bucket permutation by norm (approximate sort, exact bounds)
__global__ __launch_bounds__(1024) void bucket_kernel(){
    __shared__ int bins[NBIN];
    __shared__ int bstart[NBIN];
    __shared__ float rmn[32], rmx[32];
    __shared__ int wsum[32];
    __shared__ float s_bmn, s_bmx;
    const int t = threadIdx.x;
    const int lane = t & 31, wid = t >> 5;

    float nv[16];
    #pragma unroll
    for (int i = 0; i < 16; i++) nv[i] = sqrtf(d_sq[t*16 + i]);
    float mn = nv[0], mx = nv[0];
    #pragma unroll
    for (int i = 1; i < 16; i++){ mn = fminf(mn, nv[i]); mx = fmaxf(mx, nv[i]); }
    #pragma unroll
    for (int o = 16; o > 0; o >>= 1){
        mn = fminf(mn, __shfl_xor_sync(0xffffffffu, mn, o));
        mx = fmaxf(mx, __shfl_xor_sync(0xffffffffu, mx, o));
    }
    if (lane == 0){ rmn[wid] = mn; rmx[wid] = mx; }
    __syncthreads();
    if (t == 0){
        float a = rmn[0], b = rmx[0];
        for (int i = 1; i < 32; i++){ a = fminf(a, rmn[i]); b = fmaxf(b, rmx[i]); }
        s_bmn = a; s_bmx = b;
    }
    for (int i = t; i < NBIN; i += 1024) bins[i] = 0;
    __syncthreads();
    const float bmn = s_bmn, bmx = s_bmx;
    const float scale = (bmx > bmn) ? (float)(NBIN - 1) / (bmx - bmn) : 0.f;

    int bx[16];
    #pragma unroll
    for (int i = 0; i < 16; i++){
        int b = (int)((nv[i] - bmn) * scale);
        b = max(0, min(NBIN - 1, b));
        bx[i] = b;
        atomicAdd(&bins[b], 1);
    }
    __syncthreads();

    // exclusive scan of bins -> bstart
    int s0 = bins[t*4], s1 = bins[t*4+1], s2 = bins[t*4+2], s3 = bins[t*4+3];
    int tsum = s0 + s1 + s2 + s3;
    int sc = tsum;
    #pragma unroll
    for (int o = 1; o < 32; o <<= 1){ int n = __shfl_up_sync(0xffffffffu, sc, o); if (lane >= o) sc += n; }
    if (lane == 31) wsum[wid] = sc;
    __syncthreads();
    if (wid == 0){
        int w = wsum[lane];
        #pragma unroll
        for (int o = 1; o < 32; o <<= 1){ int n = __shfl_up_sync(0xffffffffu, w, o); if (lane >= o) w += n; }
        wsum[lane] = w;
    }
    __syncthreads();
    int base = ((wid > 0) ? wsum[wid-1] : 0) + (sc - tsum);
    bstart[t*4]   = base;
    bstart[t*4+1] = base + s0;
    bstart[t*4+2] = base + s0 + s1;
    bstart[t*4+3] = base + s0 + s1 + s2;
    __syncthreads();

    // scatter (bins reused as cursors)
    for (int i = t; i < NBIN; i += 1024) bins[i] = 0;
    __syncthreads();
    #pragma unroll
    for (int i = 0; i < 16; i++){
        int p = bstart[bx[i]] + atomicAdd(&bins[bx[i]], 1);
        d_skey[p] = nv[i];
        d_sidx16[p] = (unsigned short)(t*16 + i);
    }
}

// permute features into sorted order
__global__ void permute_kernel(int id){
    const float* f = fbuf(id);
    int gid = blockIdx.x*256 + threadIdx.x;       // 0 .. 262143
    int p = gid >> 4, q = gid & 15;
    int src = d_sidx16[p];
    ((float4*)d_fperm)[p*16 + q] = ((const float4*)(f + (size_t)src*64))[q];
}

// per-tile prefix-max (from left) and suffix-min (from right) norms
__global__ void tilestat_kernel(){
    __shared__ float tmx[KNT], tmn[KNT];
    int t = threadIdx.x;   // 128 threads
    float mx = -CUDART_INF_F, mn = CUDART_INF_F;
    for (int i = 0; i < 128; i++){
        float v = d_skey[t*128 + i];
        mx = fmaxf(mx, v); mn = fminf(mn, v);
    }
    tmx[t] = mx; tmn[t] = mn;
    __syncthreads();
    if (t == 0){
        float run = -CUDART_INF_F;
        for (int i = 0; i < KNT; i++){ run = fmaxf(run, tmx[i]); d_pmax[i] = run; }
        run = CUDART_INF_F;
        for (int i = KNT-1; i >= 0; i--){ run = fminf(run, tmn[i]); d_pmin[i] = run; }
    }
}

// fetch one 128-col tile (+norms, +u16 orig idx) into buffer nb (128 threads)
__device__ __forceinline__ void fetch_tile(int t, unsigned scol_u, unsigned ssq_u,
                                           unsigned sidx_u, int nb, int tile){
    const int cb0 = tile * 128;
    #pragma unroll
    for (int i = 0; i < 16; i++){
        int v = t + i*128; int c = v >> 4, kqp = v & 15;
        cp16(scol_u + (unsigned)(nb*32768) + (unsigned)((kqp<<11) + ((c>>3)<<7) + ((((c&7) ^ ((c>>3)&7)))<<4)),
             d_fperm + (size_t)(cb0 + c)*64 + kqp*4);
    }
    if (t < 32) cp16(ssq_u + (unsigned)(nb*512 + t*16), d_skey + cb0 + t*4);
    else if (t < 48) cp16(sidx_u + (unsigned)(nb*256 + (t-32)*16), d_sidx16 + cb0 + (t-32)*8);
}

// ---------------- kNN-64: 8x8 register-tiled GEMM + norm-bound pruning ------
// 128 threads = 8 rg x 16 cg; block = 64 rows; col tiles 128 wide, 2 bufs.
// Epilogue+selection run in two 64-col half passes so sdist is 16KB and two
// blocks co-reside per SM (phase overlap).
__global__ __launch_bounds__(128, 2) void knn64_kernel(){
    extern __shared__ char sm[];
    float* scolf = (float*)(sm + SM_SCOL);
    float* srowf = (float*)(sm + SM_SROW);
    float* sdist = (float*)(sm + SM_SDIST);
    float* ssqn  = (float*)(sm + SM_SSQ);
    unsigned short* sidxb = (unsigned short*)(sm + SM_SIDX);
    float* s_rn  = (float*)(sm + SM_RN);
    int*   s_ctl = (int*)  (sm + SM_CTL);          // [0]=nxt [1]=lo [2]=hi
    float* s_ctf = (float*)(sm + SM_CTL + 16);     // [0]=nL [1]=nR [2]=cmn [3]=cmx
    const unsigned scol_u = smaddr(scolf);
    const unsigned srow_u = smaddr(srowf);
    const unsigned ssq_u  = smaddr(ssqn);
    const unsigned sidx_u = smaddr(sidxb);
    const int t  = threadIdx.x;
    const int rg = t >> 4, cg = t & 15;
    const int c0 = blockIdx.x;                     // row chunk 0..255
    const int rbase = c0 * 64;
    const int diag = c0 >> 1;                      // own col tile
    const int selrow = t >> 1, selhalf = t & 1;

    // row tile (64 rows, swizzled) + diagonal col tile (buf 0)
    #pragma unroll
    for (int i = 0; i < 8; i++){
        int v = t + i*128; int r = v >> 4, q = v & 15;
        cp16(srow_u + (unsigned)((r<<8) + ((q ^ (r>>3)) << 4)),
             d_fperm + (size_t)(rbase + r)*64 + q*4);
    }
    fetch_tile(t, scol_u, ssq_u, sidx_u, 0, diag);
    cp_commit();

    if (t < 64) s_rn[t] = d_skey[rbase + t];
    if (t == 0){ s_ctl[1] = diag; s_ctl[2] = diag; }
    __syncthreads();
    if (t == 0){
        float cmn = s_rn[0], cmx = s_rn[0];
        for (int i = 1; i < 64; i++){ cmn = fminf(cmn, s_rn[i]); cmx = fmaxf(cmx, s_rn[i]); }
        s_ctf[2] = cmn; s_ctf[3] = cmx;
    }

    float bd[KK]; int bi[KK];
    #pragma unroll
    for (int q = 0; q < KK; q++){ bd[q] = CUDART_INF_F; bi[q] = 0x7fffffff; }
    bool anyL = (diag > 0), anyR = (diag < KNT-1);
    int cur = diag, curbuf = 0;

    while (cur >= 0){
        cp_wait0();
        __syncthreads();

        // choose next tile (expand toward nearer norm edge)
        if (t == 0){
            int lo = s_ctl[1], hi = s_ctl[2];
            bool aL = anyL && (lo > 0), aR = anyR && (hi < KNT-1);
            int nxt = -1;
            if (aL && aR){
                float eL = s_ctf[2] - d_pmax[lo-1];
                float eR = d_pmin[hi+1] - s_ctf[3];
                nxt = (eL <= eR) ? (lo - 1) : (hi + 1);
            } else if (aL) nxt = lo - 1;
            else if (aR) nxt = hi + 1;
            if (nxt >= 0){ if (nxt < lo) lo = nxt; else hi = nxt; }
            s_ctl[0] = nxt; s_ctl[1] = lo; s_ctl[2] = hi;
            s_ctf[0] = (lo > 0)      ? d_pmax[lo-1] : 0.f;
            s_ctf[1] = (hi < KNT-1)  ? d_pmin[hi+1] : 0.f;
        }
        __syncthreads();
        const int nxt = s_ctl[0];
        if (nxt >= 0) fetch_tile(t, scol_u, ssq_u, sidx_u, curbuf^1, nxt);
        cp_commit();

        // ---- GEMM: 8x8 micro-tile over k=64 (16 k-quads) ----
        const float* cbf = scolf + curbuf*8192;
        unsigned long long acc[64];
        #pragma unroll
        for (int z = 0; z < 64; z++) acc[z] = 0ull;
        #pragma unroll 4
        for (int kqp = 0; kqp < 16; kqp++){
            ulonglong2 rv[8];
            #pragma unroll
            for (int i = 0; i < 8; i++)
                rv[i] = *(const ulonglong2*)(srowf + ((rg*8+i)<<6) + ((kqp ^ rg) << 2));
            #pragma unroll
            for (int j = 0; j < 8; j++){
                ulonglong2 cv = *(const ulonglong2*)(cbf + (kqp<<9) + (cg<<5) + ((j ^ (cg&7)) << 2));
                #pragma unroll
                for (int i = 0; i < 8; i++){
                    acc[i*8+j] = ffma2(rv[i].x, cv.x, acc[i*8+j]);
                    acc[i*8+j] = ffma2(rv[i].y, cv.y, acc[i*8+j]);
                }
            }
        }

        // ---- two 64-col half passes: epilogue -> sdist, then selection ----
        #pragma unroll
        for (int H = 0; H < 2; H++){
            if ((cg >> 3) == H){
                float scv[8];
                #pragma unroll
                for (int j = 0; j < 8; j++){ float nv = ssqn[curbuf*128 + cg*8 + j]; scv[j] = nv*nv; }
                #pragma unroll
                for (int i = 0; i < 8; i++){
                    int r = rg*8 + i;
                    float rn = s_rn[r];
                    float sr = rn*rn;
                    float dj[8];
                    #pragma unroll
                    for (int j = 0; j < 8; j++)
                        dj[j] = fmaf(-2.f, hsum2(acc[i*8+j]), sr + scv[j]);
                    float4* dst = (float4*)(sdist + r*64 + (cg&7)*8);
                    dst[0] = make_float4(dj[0], dj[1], dj[2], dj[3]);
                    dst[1] = make_float4(dj[4], dj[5], dj[6], dj[7]);
                }
            }
            __syncthreads();

            // selection: 2 threads/row, 32 cols each; (dist, origidx) lexicographic
            {
                const float4* sp = (const float4*)(sdist + selrow*64 + selhalf*32);
                const unsigned short* sx = sidxb + curbuf*128 + H*64 + selhalf*32;
                #pragma unroll 4
                for (int c2 = 0; c2 < 8; c2++){
                    float4 v = sp[c2];
                    #pragma unroll
                    for (int e = 0; e < 4; e++){
                        float dv = (e==0)?v.x:(e==1)?v.y:(e==2)?v.z:v.w;
                        if (dv <= bd[KK-1]){
                            int ci = (int)sx[c2*4 + e];
                            float cd = dv;
                            #pragma unroll
                            for (int q = 0; q < KK; q++){
                                if (cd < bd[q] || (cd == bd[q] && ci < bi[q])){
                                    float td = bd[q]; int ti = bi[q];
                                    bd[q] = cd; bi[q] = ci; cd = td; ci = ti;
                                }
                            }
                        }
                    }
                }
            }
            __syncthreads();
        }

        // ---- termination flags (per-thread d10 is an over-estimate: safe) ----
        {
            const int lo2 = s_ctl[1], hi2 = s_ctl[2];
            float nr = s_rn[selrow];
            float d10 = bd[KK-1];
            bool fL = false, fR = false;
            if (lo2 > 0){ float d = nr - s_ctf[0]; fL = (d <= 0.f) || (d*d < d10); }
            if (hi2 < KNT-1){ float d = s_ctf[1] - nr; fR = (d <= 0.f) || (d*d < d10); }
            anyL = (__syncthreads_or(fL ? 1 : 0) != 0);
            anyR = (__syncthreads_or(fR ? 1 : 0) != 0);
        }
        cur = nxt; curbuf ^= 1;
    }

    // ---- final merge: 2 half-lists per row, lexicographic (dist, origidx) ----
    __syncthreads();
    float* md = sdist;
    int*   mi = (int*)(sdist + 1280);
    #pragma unroll
    for (int q = 0; q < KK; q++){
        md[(selrow*2 + selhalf)*KK + q] = bd[q];
        mi[(selrow*2 + selhalf)*KK + q] = bi[q];
    }
    __syncthreads();
    if (t < 64){
        const float* da = md + (t*2)*KK;   const int* ia = mi + (t*2)*KK;
        const float* db = md + (t*2+1)*KK; const int* ib = mi + (t*2+1)*KK;
        int orow = (int)d_sidx16[rbase + t];
        int pa = 0, pb = 0;
        #pragma unroll
        for (int q = 0; q < KK; q++){
            int par = min(pa, KK-1), pbr = min(pb, KK-1);
            float va = da[par]; int ja = ia[par];
            float vb = db[pbr]; int jb = ib[pbr];
            bool takeA;
            if (pb >= KK) takeA = true;
            else if (pa >= KK) takeA = false;
            else takeA = (va < vb) || (va == vb && ja < jb);
            d_idx[orow*KK + q] = takeA ? ja : jb;
            if (takeA) pa++; else pb++;
        }
    }
}

// ---------------- per-point projections (C=64): a = x@(Wt-Wb), c = x@Wb -----
__global__ void proj64_kernel(int id, const float* __restrict__ W){
    const float* x = fbuf(id);
    __shared__ float sWa[64*64];
    __shared__ float sWb[64*64];
    for (int v = threadIdx.x; v < 64*64; v += 256){
        float wb = W[64*64 + v];
        sWa[v] = W[v] - wb;
        sWb[v] = wb;
    }
    __syncthreads();
    int o  = threadIdx.x & 63;
    int rg = threadIdx.x >> 6;
    int row0 = blockIdx.x * 64;
    for (int rr = 0; rr < 64; rr += 4){
        int row = row0 + rr + rg;
        float av = 0.f, cv = 0.f;
        #pragma unroll
        for (int d = 0; d < 64; d++){
            float xv = __ldg(x + (long)row*64 + d);
            av += xv * sWa[d*64+o];
            cv += xv * sWb[d*64+o];
        }
        d_Abuf[row*64+o] = av; d_Cbuf[row*64+o] = cv;
    }
}

// ---------------- gather + pool (BN layers: stats + max/min) ----------------
__global__ void pool_bn_kernel(const float* __restrict__ bias){
    int o  = threadIdx.x & 63;
    int rg = threadIdx.x >> 6;
    int row = blockIdx.x*4 + rg;
    float a = d_Abuf[row*64+o] + bias[o];
    float mx = -CUDART_INF_F, mn = CUDART_INF_F, s = 0.f, s2 = 0.f;
    #pragma unroll
    for (int k = 0; k < KK; k++){
        int j = d_idx[row*KK+k];
        float h = a + d_Cbuf[j*64+o];
        mx = fmaxf(mx, h); mn = fminf(mn, h);
        s += h; s2 += h*h;
    }
    d_maxh[row*64+o] = mx; d_minh[row*64+o] = mn;
    __shared__ float reds[4][64], reds2[4][64];
    reds[rg][o] = s; reds2[rg][o] = s2;
    __syncthreads();
    if (rg == 0){
        float ts = reds[0][o]+reds[1][o]+reds[2][o]+reds[3][o];
        float t2 = reds2[0][o]+reds2[1][o]+reds2[2][o]+reds2[3][o];
        atomicAdd(&d_sum[o], ts);
        atomicAdd(&d_ss[o],  t2);
    }
}

// BN apply -> feature buffer, fused per-row squared-norm reduction
__global__ void bn_apply_sq_kernel(const float* __restrict__ gamma, const float* __restrict__ beta,
                                   int outid){
    float* out = fbuf(outid);
    int t = threadIdx.x;
    int gid = blockIdx.x*256 + t;
    int o = t & 63;
    const float inv = 1.f/(float)(NPTS*KK);
    float mu  = d_sum[o]*inv;
    float var = d_ss[o]*inv - mu*mu;
    float g = gamma[o];
    float s = rsqrtf(var + 1e-5f) * g;
    float pool = (g >= 0.f) ? d_maxh[gid] : d_minh[gid];
    float v = fmaxf(pool*s + (beta[o] - mu*s), 0.f);
    out[gid] = v;
    float w = v*v;
    #pragma unroll
    for (int off = 16; off > 0; off >>= 1) w += __shfl_xor_sync(0xffffffffu, w, off);
    __shared__ float part[8];
    if ((t & 31) == 0) part[t>>5] = w;
    __syncthreads();
    if (t < 4) d_sq[blockIdx.x*4 + t] = part[2*t] + part[2*t+1];
}

// plain pool -> feature buffer, fused per-row squared-norm + stat reset
__global__ void pool_plain_sq_kernel(const float* __restrict__ bias, int outid){
    float* out = fbuf(outid);
    int t = threadIdx.x;
    int gid = blockIdx.x*256 + t;
    int o = t & 63; int row = gid >> 6;
    float cmax = -CUDART_INF_F;
    #pragma unroll
    for (int k = 0; k < KK; k++){
        int j = d_idx[row*KK+k];
        cmax = fmaxf(cmax, d_Cbuf[j*64+o]);
    }
    float v = fmaxf(d_Abuf[gid] + bias[o] + cmax, 0.f);
    out[gid] = v;
    float w = v*v;
    #pragma unroll
    for (int off = 16; off > 0; off >>= 1) w += __shfl_xor_sync(0xffffffffu, w, off);
    __shared__ float part[8];
    if ((t & 31) == 0) part[t>>5] = w;
    __syncthreads();
    if (t < 4) d_sq[blockIdx.x*4 + t] = part[2*t] + part[2*t+1];
    if (blockIdx.x == 0 && t < 64){ d_sum[t] = 0.f; d_ss[t] = 0.f; }
}

// ---------------- head ----------------
__global__ void starts_kernel(const int* __restrict__ n_pts){
    if (threadIdx.x == 0){
        int acc = 0;
        for (int b = 0; b < 64; b++){ d_starts[b] = acc; acc += n_pts[b]; }
        d_starts[64] = acc;
    }
}

__global__ void agg_kernel(){
    int b = blockIdx.x;
    int l = threadIdx.x >> 6, o = threadIdx.x & 63;
    const float* f = (l == 0) ? d_f1 : (l == 1) ? d_f2 : (l == 2) ? d_f3 : d_f4;
    int s = min(d_starts[b], NPTS);
    int e = (b == 63) ? NPTS : min(d_starts[b+1], NPTS);
    float m = -CUDART_INF_F;
    for (int p = s; p < e; p++) m = fmaxf(m, f[p*64+o]);
    d_P[b*256 + l*64 + o] = m;
}

__global__ void final_kernel(const float* __restrict__ Wp, const float* __restrict__ bp,
                             float* __restrict__ out){
    int b = blockIdx.x; int o = threadIdx.x;  // 128 threads
    __shared__ float sp[256];
    for (int v = o; v < 256; v += 128) sp[v] = d_P[b*256+v];
    __syncthreads();
    float acc = bp[o];
    #pragma unroll 4
    for (int d = 0; d < 256; d++) acc += sp[d]*Wp[d*128+o];
    float v = tanhf(acc);
    float sq = v*v;
    #pragma unroll
    for (int off = 16; off > 0; off >>= 1) sq += __shfl_xor_sync(0xffffffffu, sq, off);
    __shared__ float rs[4];
    if ((o & 31) == 0) rs[o>>5] = sq;
    __syncthreads();
    float tot = rs[0]+rs[1]+rs[2]+rs[3];
    out[b*128+o] = v / (sqrtf(tot) + 1e-9f);
}

// ---------------- launch ----------------
extern "C" void kernel_launch(void* const* d_in, const int* in_sizes, int n_in,
                              void* d_out, int out_size){
    (void)in_sizes; (void)n_in; (void)out_size;
    const float* x     = (const float*)d_in[0];
    const int*   n_pts = (const int*)  d_in[1];
    const float* W1 = (const float*)d_in[2];  const float* b1  = (const float*)d_in[3];
    const float* g1 = (const float*)d_in[4];  const float* be1 = (const float*)d_in[5];
    const float* W2 = (const float*)d_in[6];  const float* b2  = (const float*)d_in[7];
    const float* W3 = (const float*)d_in[8];  const float* b3  = (const float*)d_in[9];
    const float* g3 = (const float*)d_in[10]; const float* be3 = (const float*)d_in[11];
    const float* W4 = (const float*)d_in[12]; const float* b4  = (const float*)d_in[13];
    const float* Wp = (const float*)d_in[14]; const float* bp  = (const float*)d_in[15];
    float* out = (float*)d_out;

    cudaFuncSetAttribute(knn64_kernel, cudaFuncAttributeMaxDynamicSharedMemorySize, SMEM_K);

    // ---- layer 1 (C=3, BN) ----
    knn3proj3_kernel<<<128, 128>>>(x, W1);
    pool_bn_kernel<<<NPTS/4, 256>>>(b1);
    bn_apply_sq_kernel<<<NPTS/4, 256>>>(g1, be1, 1);

    // ---- layer 2 (C=64, no BN) ----
    bucket_kernel<<<1, 1024>>>();
    permute_kernel<<<1024, 256>>>(1);
    tilestat_kernel<<<1, 128>>>();
    knn64_kernel<<<KNCH, 128, SMEM_K>>>();
    proj64_kernel<<<NPTS/64, 256>>>(1, W2);
    pool_plain_sq_kernel<<<NPTS/4, 256>>>(b2, 2);

    // ---- layer 3 (C=64, BN) ----
    bucket_kernel<<<1, 1024>>>();
    permute_kernel<<<1024, 256>>>(2);
    tilestat_kernel<<<1, 128>>>();
    knn64_kernel<<<KNCH, 128, SMEM_K>>>();
    proj64_kernel<<<NPTS/64, 256>>>(2, W3);
    pool_bn_kernel<<<NPTS/4, 256>>>(b3);
    bn_apply_sq_kernel<<<NPTS/4, 256>>>(g3, be3, 3);

    // ---- layer 4 (C=64, no BN) ----
    bucket_kernel<<<1, 1024>>>();
    permute_kernel<<<1024, 256>>>(3);
    tilestat_kernel<<<1, 128>>>();
    knn64_kernel<<<KNCH, 128, SMEM_K>>>();
    proj64_kernel<<<NPTS/64, 256>>>(3, W4);
    pool_plain_sq_kernel<<<NPTS/4, 256>>>(b4, 4);

    // ---- head ----
    starts_kernel<<<1, 32>>>(n_pts);
    agg_kernel<<<64, 256>>>();
    final_kernel<<<64, 128>>>(Wp, bp, out);
}

// round 17
// speedup vs baseline: 1.2746x; 1.2746x over previous
#include <cuda_runtime.h>
#include <math_constants.h>
#include <cstdint>

#define NPTS 16384
#define KK 10
#define CB 64
#define NBIN 4096

// knn64 tiling (R15 shape: 8x8 micro-tile, 256 threads, 128x128 block tile)
#define KNT 128                 /* col tiles */
#define KNCH 128                /* row chunks = grid */

// dynamic smem layout for knn64 (bytes)
#define SM_SCOL   0             /* 2 x 32768 swizzled col tiles */
#define SM_SROW   65536         /* 32768 swizzled row tile */
#define SM_SDIST  98304         /* 128 x 132 floats = 67584 */
#define SM_SSQ    165888        /* 2 x 128 col norms */
#define SM_SIDX   166912        /* 2 x 128 col orig idx */
#define SM_RN     167936        /* 128 row norms */
#define SM_RQ     168448        /* 128 row norms^2 */
#define SM_CTL    168960        /* control: 3 ints + 4 floats */
#define SMEM_K    169024

// ---------------- scratch (device globals; no allocation) ----------------
__device__ __align__(16) float d_sq[NPTS];
__device__ int   d_idx[NPTS*KK];
__device__ __align__(16) float d_f1[NPTS*CB];
__device__ __align__(16) float d_f2[NPTS*CB];
__device__ __align__(16) float d_f3[NPTS*CB];
__device__ __align__(16) float d_f4[NPTS*CB];
__device__ __align__(16) float d_fperm[NPTS*CB];
__device__ __align__(16) float d_skey[NPTS];
__device__ __align__(16) int   d_sidx[NPTS];
__device__ __align__(16) float d_pmax[KNT];
__device__ __align__(16) float d_pmin[KNT];
__device__ __align__(16) float d_Abuf[NPTS*CB];
__device__ __align__(16) float d_Cbuf[NPTS*CB];
__device__ __align__(16) float d_maxh[NPTS*CB];
__device__ __align__(16) float d_minh[NPTS*CB];
__device__ float d_sum[CB];
__device__ float d_ss[CB];
__device__ int   d_starts[65];
__device__ float d_P[64*256];

// Resolve feature-buffer id -> device pointer IN DEVICE CODE (host-side
// __device__ symbol decay passes the host shadow address under ATS).
__device__ __forceinline__ float* fbuf(int id){
    switch(id){
        case 1: return d_f1;
        case 2: return d_f2;
        case 3: return d_f3;
        default: return d_f4;
    }
}

// ---------------- packed f32x2 helpers ----------------
__device__ __forceinline__ unsigned long long ffma2(unsigned long long a, unsigned long long b, unsigned long long c){
    unsigned long long r;
    asm("fma.rn.f32x2 %0, %1, %2, %3;" : "=l"(r) : "l"(a), "l"(b), "l"(c));
    return r;
}
__device__ __forceinline__ float hsum2(unsigned long long v){
    float lo, hi;
    asm("mov.b64 {%0,%1}, %2;" : "=f"(lo), "=f"(hi) : "l"(v));
    return lo + hi;
}

// ---------------- cp.async helpers ----------------
__device__ __forceinline__ unsigned smaddr(const void* p){
    return (unsigned)__cvta_generic_to_shared(p);
}
__device__ __forceinline__ void cp16(unsigned s, const void* g){
    asm volatile("cp.async.cg.shared.global [%0], [%1], 16;" :: "r"(s), "l"(g));
}
__device__ __forceinline__ void cp_commit(){ asm volatile("cp.async.commit_group;"); }
__device__ __forceinline__ void cp_wait0(){ asm volatile("cp.async.wait_group 0;"); }

// ---------------- launch 1: fused kNN(3D) + projection(C=3) + stat reset ----
__global__ __launch_bounds__(128) void knn3proj3_kernel(const float* __restrict__ x,
                                                        const float* __restrict__ W){
    __shared__ float sWa[192], sWb[192];
    __shared__ float4 sc[256];
    const int t = threadIdx.x;
    const int i = blockIdx.x*128 + t;
    for (int v = t; v < 192; v += 128){
        float wb = W[192 + v];
        sWa[v] = W[v] - wb;
        sWb[v] = wb;
    }
    if (blockIdx.x == 0 && t < 64){ d_sum[t] = 0.f; d_ss[t] = 0.f; }
    float xi = x[i*3], yi = x[i*3+1], zi = x[i*3+2];
    float sqi = xi*xi + yi*yi + zi*zi;
    __syncthreads();

    #pragma unroll 8
    for (int o = 0; o < 64; o++){
        float av = xi*sWa[o] + yi*sWa[64+o] + zi*sWa[128+o];
        float cv = xi*sWb[o] + yi*sWb[64+o] + zi*sWb[128+o];
        d_Abuf[i*64+o] = av; d_Cbuf[i*64+o] = cv;
    }

    float bd[KK]; int bi[KK];
    #pragma unroll
    for (int q = 0; q < KK; q++){ bd[q] = CUDART_INF_F; bi[q] = 0x7fffffff; }
    for (int base = 0; base < NPTS; base += 256){
        __syncthreads();
        for (int v = t; v < 256; v += 128){
            int c = base + v;
            float xc = x[c*3], yc = x[c*3+1], zc = x[c*3+2];
            sc[v] = make_float4(xc, yc, zc, xc*xc + yc*yc + zc*zc);
        }
        __syncthreads();
        #pragma unroll 4
        for (int j = 0; j < 256; j++){
            float4 cv = sc[j];
            float dist = sqi + cv.w - 2.f*(xi*cv.x + yi*cv.y + zi*cv.z);
            if (dist < bd[KK-1]){
                float cd = dist; int ci = base + j;
                #pragma unroll
                for (int q = 0; q < KK; q++){
                    if (cd < bd[q]){ float td = bd[q]; int ti = bi[q]; bd[q] = cd; bi[q] = ci; cd = td; ci = ti; }
                }
            }
        }
    }
    #pragma unroll
    for (int q = 0; q < KK; q++) d_idx[i*KK+q] = bi[q];
}

// ---------------- bucket permutation by norm + fused per-tile stats ---------
__global__ __launch_bounds__(1024) void bucket_kernel(){
    __shared__ int bins[NBIN];
    __shared__ int bstart[NBIN];
    __shared__ float rmn[32], rmx[32];
    __shared__ int wsum[32];
    __shared__ float s_bmn, s_bmx;
    const int t = threadIdx.x;
    const int lane = t & 31, wid = t >> 5;

    float nv[16];
    #pragma unroll
    for (int i = 0; i < 16; i++) nv[i] = sqrtf(d_sq[t*16 + i]);
    float mn = nv[0], mx = nv[0];
    #pragma unroll
    for (int i = 1; i < 16; i++){ mn = fminf(mn, nv[i]); mx = fmaxf(mx, nv[i]); }
    #pragma unroll
    for (int o = 16; o > 0; o >>= 1){
        mn = fminf(mn, __shfl_xor_sync(0xffffffffu, mn, o));
        mx = fmaxf(mx, __shfl_xor_sync(0xffffffffu, mx, o));
    }
    if (lane == 0){ rmn[wid] = mn; rmx[wid] = mx; }
    __syncthreads();
    if (t == 0){
        float a = rmn[0], b = rmx[0];
        for (int i = 1; i < 32; i++){ a = fminf(a, rmn[i]); b = fmaxf(b, rmx[i]); }
        s_bmn = a; s_bmx = b;
    }
    for (int i = t; i < NBIN; i += 1024) bins[i] = 0;
    __syncthreads();
    const float bmn = s_bmn, bmx = s_bmx;
    const float scale = (bmx > bmn) ? (float)(NBIN - 1) / (bmx - bmn) : 0.f;

    int bx[16];
    #pragma unroll
    for (int i = 0; i < 16; i++){
        int b = (int)((nv[i] - bmn) * scale);
        b = max(0, min(NBIN - 1, b));
        bx[i] = b;
        atomicAdd(&bins[b], 1);
    }
    __syncthreads();

    // exclusive scan of bins -> bstart
    int s0 = bins[t*4], s1 = bins[t*4+1], s2 = bins[t*4+2], s3 = bins[t*4+3];
    int tsum = s0 + s1 + s2 + s3;
    int sc = tsum;
    #pragma unroll
    for (int o = 1; o < 32; o <<= 1){ int n = __shfl_up_sync(0xffffffffu, sc, o); if (lane >= o) sc += n; }
    if (lane == 31) wsum[wid] = sc;
    __syncthreads();
    if (wid == 0){
        int w = wsum[lane];
        #pragma unroll
        for (int o = 1; o < 32; o <<= 1){ int n = __shfl_up_sync(0xffffffffu, w, o); if (lane >= o) w += n; }
        wsum[lane] = w;
    }
    __syncthreads();
    int base = ((wid > 0) ? wsum[wid-1] : 0) + (sc - tsum);
    bstart[t*4]   = base;
    bstart[t*4+1] = base + s0;
    bstart[t*4+2] = base + s0 + s1;
    bstart[t*4+3] = base + s0 + s1 + s2;
    __syncthreads();

    // scatter (bins reused as cursors)
    for (int i = t; i < NBIN; i += 1024) bins[i] = 0;
    __syncthreads();
    #pragma unroll
    for (int i = 0; i < 16; i++){
        int p = bstart[bx[i]] + atomicAdd(&bins[bx[i]], 1);
        d_skey[p] = nv[i];
        d_sidx[p] = t*16 + i;
    }

    // ---- fused per-tile prefix-max / suffix-min (global writes of d_skey
    //      by this block are visible after __syncthreads) ----
    __syncthreads();
    float* ftmx = (float*)bins;       // reuse smem
    float* ftmn = (float*)bstart;
    if (t < KNT){
        float tmx = -CUDART_INF_F, tmn = CUDART_INF_F;
        for (int i = 0; i < 128; i++){
            float v = d_skey[t*128 + i];
            tmx = fmaxf(tmx, v); tmn = fminf(tmn, v);
        }
        ftmx[t] = tmx; ftmn[t] = tmn;
    }
    __syncthreads();
    if (t == 0){
        float run = -CUDART_INF_F;
        for (int i = 0; i < KNT; i++){ run = fmaxf(run, ftmx[i]); d_pmax[i] = run; }
        run = CUDART_INF_F;
        for (int i = KNT-1; i >= 0; i--){ run = fminf(run, ftmn[i]); d_pmin[i] = run; }
    }
}

// permute features into sorted order
__global__ void permute_kernel(int id){
    const float* f = fbuf(id);
    int gid = blockIdx.x*256 + threadIdx.x;       // 0 .. 262143
    int p = gid >> 4, q = gid & 15;
    int src = d_sidx[p];
    ((float4*)d_fperm)[p*16 + q] = ((const float4*)(f + (size_t)src*64))[q];
}

// fetch one 128-col tile (+norms, +orig idx) into buffer nb
__device__ __forceinline__ void fetch_tile(int t, unsigned scol_u, unsigned ssq_u,
                                           unsigned sidx_u, int nb, int tile){
    const int cb0 = tile * 128;
    #pragma unroll
    for (int i = 0; i < 8; i++){
        int v = t + i*256; int c = v >> 4, kqp = v & 15;
        cp16(scol_u + (unsigned)(nb*32768) + (unsigned)((kqp<<11) + ((c>>3)<<7) + ((((c&7) ^ ((c>>3)&7)))<<4)),
             d_fperm + (size_t)(cb0 + c)*64 + kqp*4);
    }
    if (t < 32) cp16(ssq_u + (unsigned)(nb*512 + t*16), d_skey + cb0 + t*4);
    else if (t < 64) cp16(sidx_u + (unsigned)(nb*512 + (t-32)*16), d_sidx + cb0 + (t-32)*4);
}

// ---------------- kNN-64: 8x8 register-tiled GEMM + norm-bound pruning ------
__global__ __launch_bounds__(256, 1) void knn64_kernel(){
    extern __shared__ char sm[];
    float* scolf = (float*)(sm + SM_SCOL);
    float* srowf = (float*)(sm + SM_SROW);
    float* sdist = (float*)(sm + SM_SDIST);
    float* ssqn  = (float*)(sm + SM_SSQ);
    int*   sidxb = (int*)  (sm + SM_SIDX);
    float* s_rn  = (float*)(sm + SM_RN);
    float* s_rq  = (float*)(sm + SM_RQ);
    int*   s_ctl = (int*)  (sm + SM_CTL);          // [0]=nxt [1]=lo [2]=hi
    float* s_ctf = (float*)(sm + SM_CTL + 16);     // [0]=nL [1]=nR [2]=cmn [3]=cmx
    const unsigned scol_u = smaddr(scolf);
    const unsigned srow_u = smaddr(srowf);
    const unsigned ssq_u  = smaddr(ssqn);
    const unsigned sidx_u = smaddr(sidxb);
    const int t  = threadIdx.x;
    const int rg = t >> 4, cg = t & 15;
    const int c0 = blockIdx.x;
    const int rbase = c0 * 128;
    const int selrow = t >> 1, selhalf = t & 1;

    // row tile (swizzled) + own col tile (buf 0)
    #pragma unroll
    for (int i = 0; i < 8; i++){
        int v = t + i*256; int r = v >> 4, q = v & 15;
        cp16(srow_u + (unsigned)((r<<8) + ((q ^ (r>>3)) << 4)),
             d_fperm + (size_t)(rbase + r)*64 + q*4);
    }
    fetch_tile(t, scol_u, ssq_u, sidx_u, 0, c0);
    cp_commit();

    if (t < 128){ float nv = d_skey[rbase + t]; s_rn[t] = nv; s_rq[t] = nv*nv; }
    if (t == 0){ s_ctl[1] = c0; s_ctl[2] = c0; }
    __syncthreads();
    if (t == 0){
        float cmn = s_rn[0], cmx = s_rn[0];
        for (int i = 1; i < 128; i++){ cmn = fminf(cmn, s_rn[i]); cmx = fmaxf(cmx, s_rn[i]); }
        s_ctf[2] = cmn; s_ctf[3] = cmx;
    }

    float bd[KK]; int bi[KK];
    #pragma unroll
    for (int q = 0; q < KK; q++){ bd[q] = CUDART_INF_F; bi[q] = 0x7fffffff; }
    bool anyL = (c0 > 0), anyR = (c0 < KNT-1);
    int cur = c0, curbuf = 0;

    while (cur >= 0){
        cp_wait0();
        __syncthreads();

        // choose next tile (expand toward nearer norm edge)
        if (t == 0){
            int lo = s_ctl[1], hi = s_ctl[2];
            bool aL = anyL && (lo > 0), aR = anyR && (hi < KNT-1);
            int nxt = -1;
            if (aL && aR){
                float eL = s_ctf[2] - d_pmax[lo-1];
                float eR = d_pmin[hi+1] - s_ctf[3];
                nxt = (eL <= eR) ? (lo - 1) : (hi + 1);
            } else if (aL) nxt = lo - 1;
            else if (aR) nxt = hi + 1;
            if (nxt >= 0){ if (nxt < lo) lo = nxt; else hi = nxt; }
            s_ctl[0] = nxt; s_ctl[1] = lo; s_ctl[2] = hi;
            s_ctf[0] = (lo > 0)      ? d_pmax[lo-1] : 0.f;
            s_ctf[1] = (hi < KNT-1)  ? d_pmin[hi+1] : 0.f;
        }
        __syncthreads();
        const int nxt = s_ctl[0];
        if (nxt >= 0) fetch_tile(t, scol_u, ssq_u, sidx_u, curbuf^1, nxt);
        cp_commit();

        // ---- GEMM: 8x8 micro-tile over k=64 (16 k-quads), cv lookahead-1 ----
        const float* cbf = scolf + curbuf*8192;
        unsigned long long acc[64];
        #pragma unroll
        for (int z = 0; z < 64; z++) acc[z] = 0ull;
        #pragma unroll 4
        for (int kqp = 0; kqp < 16; kqp++){
            ulonglong2 rv[8];
            #pragma unroll
            for (int i = 0; i < 8; i++)
                rv[i] = *(const ulonglong2*)(srowf + ((rg*8+i)<<6) + ((kqp ^ rg) << 2));
            const float* cb2 = cbf + (kqp<<9) + (cg<<5);
            ulonglong2 cv = *(const ulonglong2*)(cb2 + ((0 ^ (cg&7)) << 2));
            #pragma unroll
            for (int j = 0; j < 8; j++){
                ulonglong2 cvn = cv;
                if (j < 7) cvn = *(const ulonglong2*)(cb2 + (((j+1) ^ (cg&7)) << 2));
                #pragma unroll
                for (int i = 0; i < 8; i++){
                    acc[i*8+j] = ffma2(rv[i].x, cv.x, acc[i*8+j]);
                    acc[i*8+j] = ffma2(rv[i].y, cv.y, acc[i*8+j]);
                }
                cv = cvn;
            }
        }

        // ---- epilogue: distances -> sdist ----
        float scv[8];
        #pragma unroll
        for (int j = 0; j < 8; j++){ float nv = ssqn[curbuf*128 + cg*8 + j]; scv[j] = nv*nv; }
        #pragma unroll
        for (int i = 0; i < 8; i++){
            int r = rg*8 + i;
            float sr = s_rq[r];
            float dj[8];
            #pragma unroll
            for (int j = 0; j < 8; j++)
                dj[j] = fmaf(-2.f, hsum2(acc[i*8+j]), sr + scv[j]);
            float4* dst = (float4*)(sdist + r*132 + cg*8);
            dst[0] = make_float4(dj[0], dj[1], dj[2], dj[3]);
            dst[1] = make_float4(dj[4], dj[5], dj[6], dj[7]);
        }
        __syncthreads();

        // ---- selection: 2 threads/row, 64 cols; (dist, origidx) lexicographic
        {
            const float4* sp = (const float4*)sdist + selrow*33 + selhalf*16;
            const int* sx = sidxb + curbuf*128 + selhalf*64;
            #pragma unroll 4
            for (int c2 = 0; c2 < 16; c2++){
                float4 v = sp[c2];
                #pragma unroll
                for (int e = 0; e < 4; e++){
                    float dv = (e==0)?v.x:(e==1)?v.y:(e==2)?v.z:v.w;
                    if (dv <= bd[KK-1]){
                        int ci = sx[c2*4 + e];
                        float cd = dv;
                        #pragma unroll
                        for (int q = 0; q < KK; q++){
                            if (cd < bd[q] || (cd == bd[q] && ci < bi[q])){
                                float td = bd[q]; int ti = bi[q];
                                bd[q] = cd; bi[q] = ci; cd = td; ci = ti;
                            }
                        }
                    }
                }
            }
        }

        // ---- termination flags (row d10 bound = min of the two half-lists'
        //      10th elements: valid upper bound, tighter than per-thread) ----
        {
            const int lo2 = s_ctl[1], hi2 = s_ctl[2];
            float nr = s_rn[selrow];
            float pb9 = __shfl_xor_sync(0xffffffffu, bd[KK-1], 1);
            float d10 = fminf(bd[KK-1], pb9);
            bool fL = false, fR = false;
            if (lo2 > 0){ float d = nr - s_ctf[0]; fL = (d <= 0.f) || (d*d < d10); }
            if (hi2 < KNT-1){ float d = s_ctf[1] - nr; fR = (d <= 0.f) || (d*d < d10); }
            anyL = (__syncthreads_or(fL ? 1 : 0) != 0);
            anyR = (__syncthreads_or(fR ? 1 : 0) != 0);
        }
        cur = nxt; curbuf ^= 1;
    }

    // ---- final merge: 2 half-lists per row, lexicographic (dist, origidx) ----
    __syncthreads();
    float* md = sdist;
    int*   mi = (int*)(sdist + 2560);
    #pragma unroll
    for (int q = 0; q < KK; q++){
        md[(selrow*2 + selhalf)*KK + q] = bd[q];
        mi[(selrow*2 + selhalf)*KK + q] = bi[q];
    }
    __syncthreads();
    if (t < 128){
        const float* da = md + (t*2)*KK;   const int* ia = mi + (t*2)*KK;
        const float* db = md + (t*2+1)*KK; const int* ib = mi + (t*2+1)*KK;
        int orow = d_sidx[rbase + t];
        int pa = 0, pb = 0;
        #pragma unroll
        for (int q = 0; q < KK; q++){
            int par = min(pa, KK-1), pbr = min(pb, KK-1);
            float va = da[par]; int ja = ia[par];
            float vb = db[pbr]; int jb = ib[pbr];
            bool takeA;
            if (pb >= KK) takeA = true;
            else if (pa >= KK) takeA = false;
            else takeA = (va < vb) || (va == vb && ja < jb);
            d_idx[orow*KK + q] = takeA ? ja : jb;
            if (takeA) pa++; else pb++;
        }
    }
}

// ---------------- per-point projections (C=64): a = x@(Wt-Wb), c = x@Wb -----
__global__ void proj64_kernel(int id, const float* __restrict__ W){
    const float* x = fbuf(id);
    __shared__ float sWa[64*64];
    __shared__ float sWb[64*64];
    for (int v = threadIdx.x; v < 64*64; v += 256){
        float wb = W[64*64 + v];
        sWa[v] = W[v] - wb;
        sWb[v] = wb;
    }
    __syncthreads();
    int o  = threadIdx.x & 63;
    int rg = threadIdx.x >> 6;
    int row0 = blockIdx.x * 64;
    for (int rr = 0; rr < 64; rr += 4){
        int row = row0 + rr + rg;
        float av = 0.f, cv = 0.f;
        #pragma unroll
        for (int d = 0; d < 64; d++){
            float xv = __ldg(x + (long)row*64 + d);
            av += xv * sWa[d*64+o];
            cv += xv * sWb[d*64+o];
        }
        d_Abuf[row*64+o] = av; d_Cbuf[row*64+o] = cv;
    }
}

// ---------------- gather + pool (BN layers: stats + max/min) ----------------
__global__ void pool_bn_kernel(const float* __restrict__ bias){
    int o  = threadIdx.x & 63;
    int rg = threadIdx.x >> 6;
    int row = blockIdx.x*4 + rg;
    float a = d_Abuf[row*64+o] + bias[o];
    float mx = -CUDART_INF_F, mn = CUDART_INF_F, s = 0.f, s2 = 0.f;
    #pragma unroll
    for (int k = 0; k < KK; k++){
        int j = d_idx[row*KK+k];
        float h = a + d_Cbuf[j*64+o];
        mx = fmaxf(mx, h); mn = fminf(mn, h);
        s += h; s2 += h*h;
    }
    d_maxh[row*64+o] = mx; d_minh[row*64+o] = mn;
    __shared__ float reds[4][64], reds2[4][64];
    reds[rg][o] = s; reds2[rg][o] = s2;
    __syncthreads();
    if (rg == 0){
        float ts = reds[0][o]+reds[1][o]+reds[2][o]+reds[3][o];
        float t2 = reds2[0][o]+reds2[1][o]+reds2[2][o]+reds2[3][o];
        atomicAdd(&d_sum[o], ts);
        atomicAdd(&d_ss[o],  t2);
    }
}

// BN apply -> feature buffer, fused per-row squared-norm reduction
__global__ void bn_apply_sq_kernel(const float* __restrict__ gamma, const float* __restrict__ beta,
                                   int outid){
    float* out = fbuf(outid);
    int t = threadIdx.x;
    int gid = blockIdx.x*256 + t;
    int o = t & 63;
    const float inv = 1.f/(float)(NPTS*KK);
    float mu  = d_sum[o]*inv;
    float var = d_ss[o]*inv - mu*mu;
    float g = gamma[o];
    float s = rsqrtf(var + 1e-5f) * g;
    float pool = (g >= 0.f) ? d_maxh[gid] : d_minh[gid];
    float v = fmaxf(pool*s + (beta[o] - mu*s), 0.f);
    out[gid] = v;
    float w = v*v;
    #pragma unroll
    for (int off = 16; off > 0; off >>= 1) w += __shfl_xor_sync(0xffffffffu, w, off);
    __shared__ float part[8];
    if ((t & 31) == 0) part[t>>5] = w;
    __syncthreads();
    if (t < 4) d_sq[blockIdx.x*4 + t] = part[2*t] + part[2*t+1];
}

// plain pool -> feature buffer, fused per-row squared-norm + stat reset
__global__ void pool_plain_sq_kernel(const float* __restrict__ bias, int outid){
    float* out = fbuf(outid);
    int t = threadIdx.x;
    int gid = blockIdx.x*256 + t;
    int o = t & 63; int row = gid >> 6;
    float cmax = -CUDART_INF_F;
    #pragma unroll
    for (int k = 0; k < KK; k++){
        int j = d_idx[row*KK+k];
        cmax = fmaxf(cmax, d_Cbuf[j*64+o]);
    }
    float v = fmaxf(d_Abuf[gid] + bias[o] + cmax, 0.f);
    out[gid] = v;
    float w = v*v;
    #pragma unroll
    for (int off = 16; off > 0; off >>= 1) w += __shfl_xor_sync(0xffffffffu, w, off);
    __shared__ float part[8];
    if ((t & 31) == 0) part[t>>5] = w;
    __syncthreads();
    if (t < 4) d_sq[blockIdx.x*4 + t] = part[2*t] + part[2*t+1];
    if (blockIdx.x == 0 && t < 64){ d_sum[t] = 0.f; d_ss[t] = 0.f; }
}

// ---------------- head ----------------
__global__ void starts_kernel(const int* __restrict__ n_pts){
    if (threadIdx.x == 0){
        int acc = 0;
        for (int b = 0; b < 64; b++){ d_starts[b] = acc; acc += n_pts[b]; }
        d_starts[64] = acc;
    }
}

__global__ void agg_kernel(){
    int b = blockIdx.x;
    int l = threadIdx.x >> 6, o = threadIdx.x & 63;
    const float* f = (l == 0) ? d_f1 : (l == 1) ? d_f2 : (l == 2) ? d_f3 : d_f4;
    int s = min(d_starts[b], NPTS);
    int e = (b == 63) ? NPTS : min(d_starts[b+1], NPTS);
    float m = -CUDART_INF_F;
    for (int p = s; p < e; p++) m = fmaxf(m, f[p*64+o]);
    d_P[b*256 + l*64 + o] = m;
}

__global__ void final_kernel(const float* __restrict__ Wp, const float* __restrict__ bp,
                             float* __restrict__ out){
    int b = blockIdx.x; int o = threadIdx.x;  // 128 threads
    __shared__ float sp[256];
    for (int v = o; v < 256; v += 128) sp[v] = d_P[b*256+v];
    __syncthreads();
    float acc = bp[o];
    #pragma unroll 4
    for (int d = 0; d < 256; d++) acc += sp[d]*Wp[d*128+o];
    float v = tanhf(acc);
    float sq = v*v;
    #pragma unroll
    for (int off = 16; off > 0; off >>= 1) sq += __shfl_xor_sync(0xffffffffu, sq, off);
    __shared__ float rs[4];
    if ((o & 31) == 0) rs[o>>5] = sq;
    __syncthreads();
    float tot = rs[0]+rs[1]+rs[2]+rs[3];
    out[b*128+o] = v / (sqrtf(tot) + 1e-9f);
}

// ---------------- launch ----------------
extern "C" void kernel_launch(void* const* d_in, const int* in_sizes, int n_in,
                              void* d_out, int out_size){
    (void)in_sizes; (void)n_in; (void)out_size;
    const float* x     = (const float*)d_in[0];
    const int*   n_pts = (const int*)  d_in[1];
    const float* W1 = (const float*)d_in[2];  const float* b1  = (const float*)d_in[3];
    const float* g1 = (const float*)d_in[4];  const float* be1 = (const float*)d_in[5];
    const float* W2 = (const float*)d_in[6];  const float* b2  = (const float*)d_in[7];
    const float* W3 = (const float*)d_in[8];  const float* b3  = (const float*)d_in[9];
    const float* g3 = (const float*)d_in[10]; const float* be3 = (const float*)d_in[11];
    const float* W4 = (const float*)d_in[12]; const float* b4  = (const float*)d_in[13];
    const float* Wp = (const float*)d_in[14]; const float* bp  = (const float*)d_in[15];
    float* out = (float*)d_out;

    cudaFuncSetAttribute(knn64_kernel, cudaFuncAttributeMaxDynamicSharedMemorySize, SMEM_K);

    // ---- layer 1 (C=3, BN) ----
    knn3proj3_kernel<<<128, 128>>>(x, W1);
    pool_bn_kernel<<<NPTS/4, 256>>>(b1);
    bn_apply_sq_kernel<<<NPTS/4, 256>>>(g1, be1, 1);

    // ---- layer 2 (C=64, no BN) ----
    bucket_kernel<<<1, 1024>>>();
    permute_kernel<<<1024, 256>>>(1);
    knn64_kernel<<<KNCH, 256, SMEM_K>>>();
    proj64_kernel<<<NPTS/64, 256>>>(1, W2);
    pool_plain_sq_kernel<<<NPTS/4, 256>>>(b2, 2);

    // ---- layer 3 (C=64, BN) ----
    bucket_kernel<<<1, 1024>>>();
    permute_kernel<<<1024, 256>>>(2);
    knn64_kernel<<<KNCH, 256, SMEM_K>>>();
    proj64_kernel<<<NPTS/64, 256>>>(2, W3);
    pool_bn_kernel<<<NPTS/4, 256>>>(b3);
    bn_apply_sq_kernel<<<NPTS/4, 256>>>(g3, be3, 3);

    // ---- layer 4 (C=64, no BN) ----
    bucket_kernel<<<1, 1024>>>();
    permute_kernel<<<1024, 256>>>(3);
    knn64_kernel<<<KNCH, 256, SMEM_K>>>();
    proj64_kernel<<<NPTS/64, 256>>>(3, W4);
    pool_plain_sq_kernel<<<NPTS/4, 256>>>(b4, 4);

    // ---- head ----
    starts_kernel<<<1, 32>>>(n_pts);
    agg_kernel<<<64, 256>>>();
    final_kernel<<<64, 128>>>(Wp, bp, out);
}